// round 10
// baseline (speedup 1.0000x reference)
#include <cuda_runtime.h>
#include <cuda_bf16.h>
#include <cstdint>

// ============================================================================
// out = patches @ (w_patch @ [w_reg|w_obj]) + bias, anchor decode.
//   kD : dummy (ncu ordinal shim)
//   kA1: W2 partials (grid 24x8, block 384, d-chunks of 96)
//   kA2: reduce 8 partials -> g_Bfrag (bf16, px-permuted HMMA frag order)
//   kB : barrier-free HMMA GEMM, warp = 2 M-tiles x 6 N-tiles x 6 K-steps
//        (K-split x8), A 2-stage __ldcs prefetch, B 1-ahead __ldg.
// ============================================================================

__device__ float g_part[8 * 12 * 768 * 4];               // [p][jq][pc][4]
__device__ __align__(16) unsigned int g_Bfrag[48 * 6 * 32 * 2];

// ---------------------------------------------------------------------------
__global__ void kD() { if (threadIdx.x == 0) g_part[0] = 0.f; }

// ---------------------------------------------------------------------------
// kA1: grid (24, 8), block 384. CTA = 32 pc-rows x 96 d x 48 j.
// ---------------------------------------------------------------------------
__global__ void __launch_bounds__(384) kA1(const float* __restrict__ w_patch,
                                           const float* __restrict__ w_reg,
                                           const float* __restrict__ w_obj)
{
    __shared__ __align__(16) float sWc[96 * 48];
    __shared__ float sWp[32 * 97];

    const int tid = threadIdx.x;
    const int r0  = blockIdx.x * 32;
    const int d0  = blockIdx.y * 96;

    #pragma unroll
    for (int i = tid; i < 96 * 48; i += 384) {
        int d = i / 48, j = i % 48;
        float v = 0.f;
        if (j < 36)       v = w_reg[(size_t)(d0 + d) * 36 + j];
        else if (j < 45)  v = w_obj[(size_t)(d0 + d) * 9 + (j - 36)];
        sWc[i] = v;
    }
    #pragma unroll
    for (int i = tid; i < 32 * 96; i += 384) {
        int r = i / 96, d = i % 96;
        sWp[r * 97 + d] = w_patch[(size_t)(r0 + r) * 768 + d0 + d];
    }
    __syncthreads();

    const int jq = tid >> 5;          // warp-uniform -> broadcast LDS
    const int rl = tid & 31;
    float4 acc = make_float4(0.f, 0.f, 0.f, 0.f);
    #pragma unroll 8
    for (int dd = 0; dd < 96; ++dd) {
        float4 w = *(const float4*)&sWc[dd * 48 + jq * 4];
        float  a = sWp[rl * 97 + dd];
        acc.x += a * w.x; acc.y += a * w.y; acc.z += a * w.z; acc.w += a * w.w;
    }
    ((float4*)g_part)[((size_t)blockIdx.y * 12 + jq) * 768 + r0 + rl] = acc;
}

// ---------------------------------------------------------------------------
// kA2: reduce 8 partials; bf16 frags, px-permuted k mapping:
//   px = pc&15, q = px&3, t4p = px>>2, k = (q<2) ? 2*t4p+q : 8+2*t4p+(q-2)
// ---------------------------------------------------------------------------
__global__ void kA2()
{
    int t = blockIdx.x * 256 + threadIdx.x;
    if (t >= 9216) return;
    const int jq = t / 768, pc = t % 768;
    const float4* p = (const float4*)g_part;
    float4 s = make_float4(0.f, 0.f, 0.f, 0.f);
    #pragma unroll
    for (int k = 0; k < 8; ++k) {
        float4 v = p[((size_t)k * 12 + jq) * 768 + pc];
        s.x += v.x; s.y += v.y; s.z += v.z; s.w += v.w;
    }
    float sv[4] = {s.x, s.y, s.z, s.w};
    const int st = pc >> 4, px = pc & 15;
    const int q = px & 3, t4p = px >> 2;
    const int k = (q < 2) ? (2 * t4p + q) : (8 + 2 * t4p + (q - 2));
    unsigned short* dst = (unsigned short*)g_Bfrag;
    #pragma unroll
    for (int c = 0; c < 4; ++c) {
        int j = jq * 4 + c;
        int tf = j >> 3;
        int lane = ((j & 7) << 2) | ((k >> 1) & 3);
        __nv_bfloat16 v = __float2bfloat16_rn(sv[c]);
        dst[(((st * 6 + tf) * 32 + lane) * 2 + (k >> 3)) * 2 + (k & 1)] =
            *(unsigned short*)&v;
    }
}

// ---------------------------------------------------------------------------
// kB: grid 1024 (b*32 + fy), block 256 = 8 warps. CTA = 32 cells (fy row).
// Warp wid = ks (0..7): 6 K-steps, 2 M-tiles (cells 0-15, 16-31), 6 N-tiles.
// ---------------------------------------------------------------------------
#define SPART_OFF 0
#define BIAS_OFF  50176
#define TK_OFF    50368
#define TQ_OFF    50432
#define TBW_OFF   50496
#define TBH_OFF   50544
#define SMEMB     50624

__global__ void __launch_bounds__(256, 2) kB(
    const float* __restrict__ img,
    const float* __restrict__ b_reg,
    const float* __restrict__ b_obj,
    float* __restrict__ out)
{
    extern __shared__ __align__(16) char sm[];
    const int tid  = threadIdx.x;
    const int wid  = tid >> 5;
    const int lane = tid & 31;
    const int fy   = blockIdx.x & 31;
    const int b    = blockIdx.x >> 5;

    if (tid < 48) ((float*)(sm + BIAS_OFF))[tid] =
        (tid < 36) ? b_reg[tid] : ((tid < 45) ? b_obj[tid - 36] : 0.f);
    if (tid < 63) {
        ((unsigned char*)(sm + TK_OFF))[tid] = (unsigned char)(tid / 7);
        ((unsigned char*)(sm + TQ_OFF))[tid] = (unsigned char)(tid % 7);
    }
    if (tid < 9) {
        ((float*)(sm + TBW_OFF))[tid] = (float)(2 << (tid % 3));
        ((float*)(sm + TBH_OFF))[tid] = (float)(2 << (tid / 3));
    }

    const int ks = wid;                  // K eighth: steps ks*6 .. ks*6+5
    const int g  = lane >> 2;
    const int t4 = lane & 3;
    const int s0 = ks * 6;

    // lane A base: cell g (fx=g), px 4*t4. +128 floats = +8 cells.
    const float* base = img + ((size_t)(b * 3) * 512 + (size_t)fy * 16) * 512
                      + g * 16 + 4 * t4;

    #define SOFF(s) ((size_t)((((s) >> 4) << 9) + ((s) & 15)) << 9)

    float d[2][6][4];
    #pragma unroll
    for (int m = 0; m < 2; ++m)
        #pragma unroll
        for (int t = 0; t < 6; ++t)
            #pragma unroll
            for (int q = 0; q < 4; ++q) d[m][t][q] = 0.f;

    const uint2* __restrict__ Bf = (const uint2*)g_Bfrag;

    #define LOADA(A_, s) do {                        \
        const float* p_ = base + SOFF(s);            \
        A_[0] = __ldcs((const float4*)(p_));         \
        A_[1] = __ldcs((const float4*)(p_ + 128));   \
        A_[2] = __ldcs((const float4*)(p_ + 256));   \
        A_[3] = __ldcs((const float4*)(p_ + 384));   \
    } while (0)

    #define LOADB(B_, s) do {                                    \
        _Pragma("unroll")                                        \
        for (int t_ = 0; t_ < 6; ++t_)                           \
            B_[t_] = __ldg(&Bf[((s) * 6 + t_) * 32 + lane]);     \
    } while (0)

    #define COMPUTE(A_, B_) do {                                              \
        _Pragma("unroll")                                                     \
        for (int m_ = 0; m_ < 2; ++m_) {                                      \
            uint32_t a0_, a1_, a2_, a3_;                                      \
            { __nv_bfloat162 h_ = __float22bfloat162_rn(make_float2(A_[2*m_].x,   A_[2*m_].y));   a0_ = *(uint32_t*)&h_; } \
            { __nv_bfloat162 h_ = __float22bfloat162_rn(make_float2(A_[2*m_+1].x, A_[2*m_+1].y)); a1_ = *(uint32_t*)&h_; } \
            { __nv_bfloat162 h_ = __float22bfloat162_rn(make_float2(A_[2*m_].z,   A_[2*m_].w));   a2_ = *(uint32_t*)&h_; } \
            { __nv_bfloat162 h_ = __float22bfloat162_rn(make_float2(A_[2*m_+1].z, A_[2*m_+1].w)); a3_ = *(uint32_t*)&h_; } \
            _Pragma("unroll")                                                 \
            for (int t_ = 0; t_ < 6; ++t_)                                    \
                asm volatile(                                                 \
                    "mma.sync.aligned.m16n8k16.row.col.f32.bf16.bf16.f32 "    \
                    "{%0,%1,%2,%3}, {%4,%5,%6,%7}, {%8,%9}, {%0,%1,%2,%3};"   \
                    : "+f"(d[m_][t_][0]), "+f"(d[m_][t_][1]),                 \
                      "+f"(d[m_][t_][2]), "+f"(d[m_][t_][3])                  \
                    : "r"(a0_), "r"(a1_), "r"(a2_), "r"(a3_),                 \
                      "r"(B_[t_].x), "r"(B_[t_].y));                          \
        }                                                                     \
    } while (0)

    float4 A0[4], A1[4];
    uint2  B0[6], B1[6];
    LOADA(A0, s0);
    LOADA(A1, s0 + 1);
    LOADB(B0, s0);

    #pragma unroll
    for (int i = 0; i < 3; ++i) {
        const int s  = s0 + 2 * i;
        const int n0 = (2 * i + 2 < 6) ? s + 2 : s0 + 5;
        const int n1 = (2 * i + 3 < 6) ? s + 3 : s0 + 5;
        LOADB(B1, s + 1);
        COMPUTE(A0, B0);
        LOADA(A0, n0);
        LOADB(B0, n0);
        COMPUTE(A1, B1);
        LOADA(A1, n1);
    }

    // ---- epilogue: partials to sPart[ks][32][49] ----
    float* sPart = (float*)(sm + SPART_OFF);
    float* sBias = (float*)(sm + BIAS_OFF);
    #pragma unroll
    for (int m = 0; m < 2; ++m) {
        #pragma unroll
        for (int cc = 0; cc < 2; ++cc) {
            const int cell = m * 16 + cc * 8 + g;
            float* dst = sPart + (ks * 32 + cell) * 49;
            #pragma unroll
            for (int t = 0; t < 6; ++t) {
                const int j = t * 8 + t4 * 2;
                dst[j]     = d[m][t][2 * cc];
                dst[j + 1] = d[m][t][2 * cc + 1];
            }
        }
    }
    __syncthreads();

    // ---- reduce 8 ks partials (+bias) into sPart[0] ----
    #pragma unroll
    for (int i = 0; i < 7; ++i) {
        int idx = tid + 256 * i;
        if (idx < 32 * 49) {
            int j = idx % 49;
            if (j < 48) {
                float s = sBias[j];
                #pragma unroll
                for (int p = 0; p < 8; ++p) s += sPart[idx + p * 32 * 49];
                sPart[idx] = s;
            }
        }
    }
    __syncthreads();

    // ---- decode + coalesced store: 32 cells * 63 = 2016 floats ----
    const unsigned char* tK = (const unsigned char*)(sm + TK_OFF);
    const unsigned char* tQ = (const unsigned char*)(sm + TQ_OFF);
    const float* tBW = (const float*)(sm + TBW_OFF);
    const float* tBH = (const float*)(sm + TBH_OFF);
    float* obase = out + (size_t)blockIdx.x * 2016;
    const float bb_f = (float)b;
    const float fy_f = (float)fy * 16.f;

    int cell = tid / 63;
    int r    = tid - cell * 63;
    int idx  = tid;
    #pragma unroll
    for (int i = 0; i < 8; ++i) {
        if (idx < 2016) {
            const int k = tK[r], q = tQ[r];
            const float* v = sPart + cell * 49;
            float res;
            if (q == 0)      res = (float)cell * 16.f + v[4 * k];
            else if (q == 1) res = fy_f + v[4 * k + 1];
            else if (q == 2) res = (float)cell * 16.f + v[4 * k] + tBW[k] * v[4 * k + 2];
            else if (q == 3) res = fy_f + v[4 * k + 1] + tBH[k] * v[4 * k + 3];
            else if (q == 4) res = bb_f;
            else if (q == 5) res = 1.f / (1.f + __expf(-v[36 + k]));
            else             res = (float)k;
            obase[idx] = res;
        }
        idx += 256; r += 4; cell += 4;
        if (r >= 63) { r -= 63; cell++; }
    }
}

// ---------------------------------------------------------------------------
extern "C" void kernel_launch(void* const* d_in, const int* in_sizes, int n_in,
                              void* d_out, int out_size)
{
    const float* img     = (const float*)d_in[0];
    const float* w_patch = (const float*)d_in[1];
    const float* w_reg   = (const float*)d_in[2];
    const float* b_reg   = (const float*)d_in[3];
    const float* w_obj   = (const float*)d_in[4];
    const float* b_obj   = (const float*)d_in[5];
    float* out = (float*)d_out;

    kD<<<1, 32>>>();                              // ordinal shim for ncu
    kA1<<<dim3(24, 8), 384>>>(w_patch, w_reg, w_obj);
    kA2<<<36, 256>>>();

    cudaFuncSetAttribute(kB, cudaFuncAttributeMaxDynamicSharedMemorySize, SMEMB);
    kB<<<1024, 256, SMEMB>>>(img, b_reg, b_obj, out);
}

// round 12
// speedup vs baseline: 1.1355x; 1.1355x over previous
#include <cuda_runtime.h>
#include <cuda_bf16.h>
#include <cstdint>

// ============================================================================
// out = patches @ (w_patch @ [w_reg|w_obj]) + bias, anchor decode.
//   kD : dummy (ncu ordinal shim)
//   kA1: W2 partials (grid 24x24, block 384, d-chunks of 32)
//   kA2: reduce 24 partials -> g_Bfrag (bf16, px-permuted HMMA frag order)
//   kB : HMMA GEMM with PER-WARP cp.async pipelines (4-deep ring,
//        wait->read->refill order fixes the R11 overwrite race),
//        K-split x4, N-split x2, grid 2048 x 256.
// ============================================================================

__device__ float g_part[24 * 12 * 768 * 4];              // [p][jq][pc][4]
__device__ __align__(16) unsigned int g_Bfrag[48 * 6 * 32 * 2];

__device__ __forceinline__ uint32_t smem_u32(const void* p) {
    uint32_t a;
    asm("{ .reg .u64 t; cvta.to.shared.u64 t, %1; cvt.u32.u64 %0, t; }"
        : "=r"(a) : "l"(p));
    return a;
}
template<int N> __device__ __forceinline__ void cpwait() {
    asm volatile("cp.async.wait_group %0;" :: "n"(N));
}

// ---------------------------------------------------------------------------
__global__ void kD() { if (threadIdx.x == 0) g_part[0] = 0.f; }

// ---------------------------------------------------------------------------
// kA1: grid (24, 24), block 384. CTA = 32 pc-rows x 32 d x 48 j.
// ---------------------------------------------------------------------------
__global__ void __launch_bounds__(384) kA1(const float* __restrict__ w_patch,
                                           const float* __restrict__ w_reg,
                                           const float* __restrict__ w_obj)
{
    __shared__ __align__(16) float sWc[32 * 48];
    __shared__ float sWp[32 * 33];

    const int tid = threadIdx.x;
    const int r0  = blockIdx.x * 32;
    const int d0  = blockIdx.y * 32;

    #pragma unroll
    for (int i = tid; i < 32 * 48; i += 384) {
        int d = i / 48, j = i % 48;
        float v = 0.f;
        if (j < 36)       v = w_reg[(size_t)(d0 + d) * 36 + j];
        else if (j < 45)  v = w_obj[(size_t)(d0 + d) * 9 + (j - 36)];
        sWc[i] = v;
    }
    #pragma unroll
    for (int i = tid; i < 32 * 32; i += 384) {
        int r = i >> 5, d = i & 31;
        sWp[r * 33 + d] = w_patch[(size_t)(r0 + r) * 768 + d0 + d];
    }
    __syncthreads();

    const int jq = tid >> 5;          // warp-uniform -> broadcast LDS
    const int rl = tid & 31;
    float4 acc = make_float4(0.f, 0.f, 0.f, 0.f);
    #pragma unroll
    for (int dd = 0; dd < 32; ++dd) {
        float4 w = *(const float4*)&sWc[dd * 48 + jq * 4];
        float  a = sWp[rl * 33 + dd];
        acc.x += a * w.x; acc.y += a * w.y; acc.z += a * w.z; acc.w += a * w.w;
    }
    ((float4*)g_part)[((size_t)blockIdx.y * 12 + jq) * 768 + r0 + rl] = acc;
}

// ---------------------------------------------------------------------------
// kA2: reduce 24 partials; bf16 frags, px-permuted k mapping:
//   px = pc&15, q = px&3, t4p = px>>2, k = (q<2) ? 2*t4p+q : 8+2*t4p+(q-2)
// ---------------------------------------------------------------------------
__global__ void kA2()
{
    int t = blockIdx.x * 256 + threadIdx.x;
    if (t >= 9216) return;
    const int jq = t / 768, pc = t % 768;
    const float4* p = (const float4*)g_part;
    float4 s = make_float4(0.f, 0.f, 0.f, 0.f);
    #pragma unroll
    for (int k = 0; k < 24; ++k) {
        float4 v = p[((size_t)k * 12 + jq) * 768 + pc];
        s.x += v.x; s.y += v.y; s.z += v.z; s.w += v.w;
    }
    float sv[4] = {s.x, s.y, s.z, s.w};
    const int st = pc >> 4, px = pc & 15;
    const int q = px & 3, t4p = px >> 2;
    const int k = (q < 2) ? (2 * t4p + q) : (8 + 2 * t4p + (q - 2));
    unsigned short* dst = (unsigned short*)g_Bfrag;
    #pragma unroll
    for (int c = 0; c < 4; ++c) {
        int j = jq * 4 + c;
        int tf = j >> 3;
        int lane = ((j & 7) << 2) | ((k >> 1) & 3);
        __nv_bfloat16 v = __float2bfloat16_rn(sv[c]);
        dst[(((st * 6 + tf) * 32 + lane) * 2 + (k >> 3)) * 2 + (k & 1)] =
            *(unsigned short*)&v;
    }
}

// ---------------------------------------------------------------------------
// kB: grid 2048 = ((b*32 + fy)*2 + cg), block 256 = 8 warps, 16 cells/CTA.
// Warp w: ks = w>>1 (12 K-steps), ns = w&1 (3 B-tiles).
// A: per-warp cp.async.cg pipeline, 4 stages x 1KB (wait->read->refill).
// B: 1-ahead __ldg double buffer (L1-resident).
// ---------------------------------------------------------------------------
#define SPART_OFF 0            // reused after mainloop (needs 12544 B)
#define BIAS_OFF  32768
#define TK_OFF    32960
#define TQ_OFF    33024
#define TBW_OFF   33088
#define TBH_OFF   33136
#define SMEMB     33216

__global__ void __launch_bounds__(256, 5) kB(
    const float* __restrict__ img,
    const float* __restrict__ b_reg,
    const float* __restrict__ b_obj,
    float* __restrict__ out)
{
    extern __shared__ __align__(16) char sm[];
    const uint32_t smem = smem_u32(sm);
    const int tid  = threadIdx.x;
    const int wid  = tid >> 5;
    const int lane = tid & 31;
    const int cg   = blockIdx.x & 1;
    const int fy   = (blockIdx.x >> 1) & 31;
    const int b    = blockIdx.x >> 6;

    if (tid < 48) ((float*)(sm + BIAS_OFF))[tid] =
        (tid < 36) ? b_reg[tid] : ((tid < 45) ? b_obj[tid - 36] : 0.f);
    if (tid < 63) {
        ((unsigned char*)(sm + TK_OFF))[tid] = (unsigned char)(tid / 7);
        ((unsigned char*)(sm + TQ_OFF))[tid] = (unsigned char)(tid % 7);
    }
    if (tid < 9) {
        ((float*)(sm + TBW_OFF))[tid] = (float)(2 << (tid % 3));
        ((float*)(sm + TBH_OFF))[tid] = (float)(2 << (tid / 3));
    }

    const int ks = wid >> 1;
    const int ns = wid & 1;
    const int g  = lane >> 2;
    const int t4 = lane & 3;
    const int s0 = ks * 12;

    const float* base = img + ((size_t)(b * 3) * 512 + (size_t)fy * 16) * 512
                      + (cg * 16 + g) * 16 + 4 * t4;

    #define SOFF(s) ((size_t)((((s) >> 4) << 9) + ((s) & 15)) << 9)

    float d[3][4];
    #pragma unroll
    for (int t = 0; t < 3; ++t)
        #pragma unroll
        for (int q = 0; q < 4; ++q) d[t][q] = 0.f;

    const uint2* __restrict__ Bf = (const uint2*)g_Bfrag;
    const uint32_t sa = smem + wid * 4096 + lane * 16;   // per-warp pipeline

    #define CPA(i, s) do {                                                    \
        const float* p_ = base + SOFF(s);                                     \
        uint32_t d_ = sa + ((i) & 3) * 1024;                                  \
        asm volatile("cp.async.cg.shared.global [%0], [%1], 16;"              \
                     :: "r"(d_), "l"(p_) : "memory");                         \
        asm volatile("cp.async.cg.shared.global [%0], [%1], 16;"              \
                     :: "r"(d_ + 512), "l"(p_ + 128) : "memory");             \
        asm volatile("cp.async.commit_group;" ::: "memory");                  \
    } while (0)

    #define LOADB(B_, s) do {                                    \
        _Pragma("unroll")                                        \
        for (int t_ = 0; t_ < 3; ++t_)                           \
            B_[t_] = __ldg(&Bf[((s) * 6 + ns * 3 + t_) * 32 + lane]); \
    } while (0)

    #define COMPUTE(f0_, f1_, B_) do {                                        \
        uint32_t a0_, a1_, a2_, a3_;                                          \
        { __nv_bfloat162 h_ = __float22bfloat162_rn(make_float2(f0_.x, f0_.y)); a0_ = *(uint32_t*)&h_; } \
        { __nv_bfloat162 h_ = __float22bfloat162_rn(make_float2(f1_.x, f1_.y)); a1_ = *(uint32_t*)&h_; } \
        { __nv_bfloat162 h_ = __float22bfloat162_rn(make_float2(f0_.z, f0_.w)); a2_ = *(uint32_t*)&h_; } \
        { __nv_bfloat162 h_ = __float22bfloat162_rn(make_float2(f1_.z, f1_.w)); a3_ = *(uint32_t*)&h_; } \
        _Pragma("unroll")                                                     \
        for (int t_ = 0; t_ < 3; ++t_)                                        \
            asm volatile(                                                     \
                "mma.sync.aligned.m16n8k16.row.col.f32.bf16.bf16.f32 "        \
                "{%0,%1,%2,%3}, {%4,%5,%6,%7}, {%8,%9}, {%0,%1,%2,%3};"       \
                : "+f"(d[t_][0]), "+f"(d[t_][1]), "+f"(d[t_][2]), "+f"(d[t_][3]) \
                : "r"(a0_), "r"(a1_), "r"(a2_), "r"(a3_),                     \
                  "r"(B_[t_].x), "r"(B_[t_].y));                              \
    } while (0)

    uint2 B0[3], B1[3];
    CPA(0, s0); CPA(1, s0 + 1); CPA(2, s0 + 2); CPA(3, s0 + 3);
    LOADB(B0, s0);

    // FIXED ORDER: wait -> read stage into regs -> refill same buffer -> MMA.
    // In-thread LSU ordering: the LDS reads execute before the later
    // cp.async can write the buffer, so the 4-deep ring is race-free.
    #define STEP(i, W) do {                                                   \
        if ((i) + 1 < 12) { if ((i) & 1) LOADB(B0, s0 + (i) + 1);             \
                            else         LOADB(B1, s0 + (i) + 1); }           \
        cpwait<W>();                                                          \
        const float4* ps_ = (const float4*)(sm + wid * 4096                   \
                            + ((i) & 3) * 1024 + lane * 16);                  \
        float4 f0_ = ps_[0];                                                  \
        float4 f1_ = ps_[32];                                                 \
        if ((i) + 4 < 12) CPA((i) + 4, s0 + (i) + 4);                         \
        if ((i) & 1) COMPUTE(f0_, f1_, B1);                                   \
        else         COMPUTE(f0_, f1_, B0);                                   \
    } while (0)

    STEP(0, 3);  STEP(1, 3);  STEP(2, 3);  STEP(3, 3);
    STEP(4, 3);  STEP(5, 3);  STEP(6, 3);  STEP(7, 3);
    STEP(8, 3);  STEP(9, 2);  STEP(10, 1); STEP(11, 0);

    // ---- all warps done with pipeline smem before reuse ----
    __syncthreads();

    // ---- epilogue: partials to sPart[ks][16][49] (ns halves disjoint j) ----
    float* sPart = (float*)(sm + SPART_OFF);
    float* sBias = (float*)(sm + BIAS_OFF);
    #pragma unroll
    for (int cc = 0; cc < 2; ++cc) {
        const int cell = g + cc * 8;
        float* dst = sPart + (ks * 16 + cell) * 49;
        #pragma unroll
        for (int t = 0; t < 3; ++t) {
            const int j = (ns * 3 + t) * 8 + t4 * 2;
            dst[j]     = d[t][2 * cc];
            dst[j + 1] = d[t][2 * cc + 1];
        }
    }
    __syncthreads();

    // ---- reduce 4 ks partials (+bias) into sPart[0] ----
    #pragma unroll
    for (int i = 0; i < 4; ++i) {
        int idx = tid + 256 * i;
        if (idx < 16 * 49) {
            int j = idx % 49;
            if (j < 48) {
                sPart[idx] = sPart[idx] + sPart[idx + 16 * 49]
                           + sPart[idx + 2 * 16 * 49] + sPart[idx + 3 * 16 * 49]
                           + sBias[j];
            }
        }
    }
    __syncthreads();

    // ---- decode + coalesced store: 16 cells * 63 = 1008 floats ----
    const unsigned char* tK = (const unsigned char*)(sm + TK_OFF);
    const unsigned char* tQ = (const unsigned char*)(sm + TQ_OFF);
    const float* tBW = (const float*)(sm + TBW_OFF);
    const float* tBH = (const float*)(sm + TBH_OFF);
    float* obase = out + (size_t)blockIdx.x * 1008;
    const float bb_f = (float)b;
    const float fy_f = (float)fy * 16.f;
    const float fx0  = (float)(cg * 16);

    int cell = tid / 63;
    int r    = tid - cell * 63;
    int idx  = tid;
    #pragma unroll
    for (int i = 0; i < 4; ++i) {
        if (idx < 1008) {
            const int k = tK[r], q = tQ[r];
            const float* v = sPart + cell * 49;
            float res;
            if (q == 0)      res = (fx0 + (float)cell) * 16.f + v[4 * k];
            else if (q == 1) res = fy_f + v[4 * k + 1];
            else if (q == 2) res = (fx0 + (float)cell) * 16.f + v[4 * k] + tBW[k] * v[4 * k + 2];
            else if (q == 3) res = fy_f + v[4 * k + 1] + tBH[k] * v[4 * k + 3];
            else if (q == 4) res = bb_f;
            else if (q == 5) res = 1.f / (1.f + __expf(-v[36 + k]));
            else             res = (float)k;
            obase[idx] = res;
        }
        idx += 256; r += 4; cell += 4;
        if (r >= 63) { r -= 63; cell++; }
    }
}

// ---------------------------------------------------------------------------
extern "C" void kernel_launch(void* const* d_in, const int* in_sizes, int n_in,
                              void* d_out, int out_size)
{
    const float* img     = (const float*)d_in[0];
    const float* w_patch = (const float*)d_in[1];
    const float* w_reg   = (const float*)d_in[2];
    const float* b_reg   = (const float*)d_in[3];
    const float* w_obj   = (const float*)d_in[4];
    const float* b_obj   = (const float*)d_in[5];
    float* out = (float*)d_out;

    kD<<<1, 32>>>();                              // ordinal shim for ncu
    kA1<<<dim3(24, 24), 384>>>(w_patch, w_reg, w_obj);
    kA2<<<36, 256>>>();

    cudaFuncSetAttribute(kB, cudaFuncAttributeMaxDynamicSharedMemorySize, SMEMB);
    kB<<<2048, 256, SMEMB>>>(img, b_reg, b_obj, out);
}